// round 1
// baseline (speedup 1.0000x reference)
#include <cuda_runtime.h>
#include <cstdint>

// Binary 3x3 conv, SAME pad, stride 1.
// inputs: (32,56,56,256) f32 NHWC ; kernel: (3,3,256,256) f32 HWIO ; out: (32,56,56,256) f32
//
// Strategy: pack sign bits (bit = v > 0) of inputs and weights; per output:
//   dot = sum_{valid taps} (256 - 2*popc(xsign ^ wsign))
// Out-of-bounds taps skipped entirely (== zero-padding contributing 0).
// Exact-zero values (sign 0) are recorded and fixed by correction kernels
// (atomic ±1 adjustments), so the result is bit-exact vs the reference.

#define NB    32
#define HH    56
#define WW    56
#define CC    256
#define OO    256
#define PIX   (NB*HH*WW)          // 100352
#define CW    8                   // 256 channels / 32 bits
#define NTAP  9
#define MAXZ  8192

__device__ uint32_t g_XS[PIX * CW];          // packed input sign bits
__device__ uint32_t g_WS[NTAP * CW * OO];    // packed weight sign bits, [t][word][o]
__device__ int g_cntX, g_cntW;
__device__ int g_zX[MAXZ];                   // pix*256 + c
__device__ int g_zW[MAXZ];                   // (t*256 + c)*256 + o

__global__ void k_init() {
    g_cntX = 0;
    g_cntW = 0;
}

// One block (256 threads) per pixel: ballot sign bits.
__global__ void k_packX(const float* __restrict__ in) {
    const int pix = blockIdx.x;
    const int c = threadIdx.x;
    float v = in[(size_t)pix * CC + c];
    unsigned bit = (v > 0.0f) ? 1u : 0u;
    unsigned m = __ballot_sync(0xffffffffu, bit);
    if ((c & 31) == 0) g_XS[pix * CW + (c >> 5)] = m;
    if (v == 0.0f) {
        int i = atomicAdd(&g_cntX, 1);
        if (i < MAXZ) g_zX[i] = pix * 256 + c;
    }
}

// 72 blocks: (tap, word). thread = output channel o. Coalesced in o.
__global__ void k_packW(const float* __restrict__ kw) {
    const int b = blockIdx.x;
    const int t = b >> 3;       // tap 0..8
    const int k = b & 7;        // word 0..7
    const int o = threadIdx.x;
    unsigned wd = 0;
#pragma unroll
    for (int j = 0; j < 32; ++j) {
        int c = k * 32 + j;
        float v = kw[((size_t)(t * CC + c)) * OO + o];
        if (v > 0.0f) wd |= (1u << j);
        if (v == 0.0f) {
            int i = atomicAdd(&g_cntW, 1);
            if (i < MAXZ) g_zW[i] = (t * 256 + c) * 256 + o;
        }
    }
    g_WS[(t * CW + k) * OO + o] = wd;
}

#define POP8(A, B, T) \
    (__popc((A).x ^ w[T][0]) + __popc((A).y ^ w[T][1]) + \
     __popc((A).z ^ w[T][2]) + __popc((A).w ^ w[T][3]) + \
     __popc((B).x ^ w[T][4]) + __popc((B).y ^ w[T][5]) + \
     __popc((B).z ^ w[T][6]) + __popc((B).w ^ w[T][7]))

// Block = one (n, y) row; thread = output channel o; iterate x = 0..55.
__global__ void __launch_bounds__(256, 2) k_main(float* __restrict__ out) {
    __shared__ uint32_t sh[3 * WW * CW];   // rows y-1, y, y+1
    const int ny = blockIdx.x;             // n*56 + y
    const int n = ny / HH;
    const int y = ny % HH;
    const int o = threadIdx.x;

    uint32_t w[NTAP][CW];
#pragma unroll
    for (int t = 0; t < NTAP; ++t)
#pragma unroll
        for (int k = 0; k < CW; ++k)
            w[t][k] = g_WS[(t * CW + k) * OO + o];

    for (int idx = threadIdx.x; idx < 3 * WW * CW; idx += 256) {
        int r = idx / (WW * CW);
        int rem = idx % (WW * CW);
        int yy = y + r - 1;
        uint32_t v = 0;
        if (yy >= 0 && yy < HH)
            v = g_XS[((size_t)(n * HH + yy) * WW) * CW + rem];
        sh[idx] = v;
    }
    __syncthreads();

    float* orow = out + (size_t)ny * WW * OO + o;
    for (int x = 0; x < WW; ++x) {
        int base = 0, neg = 0;
#pragma unroll
        for (int r = 0; r < 3; ++r) {
            int yy = y + r - 1;
            if (yy < 0 || yy >= HH) continue;
#pragma unroll
            for (int s = 0; s < 3; ++s) {
                int xx = x + s - 1;
                if ((unsigned)xx >= (unsigned)WW) continue;
                const uint4* p = (const uint4*)&sh[(r * WW + xx) * CW];
                uint4 a = p[0];
                uint4 b = p[1];
                base += 256;
                const int t = r * 3 + s;
                neg += POP8(a, b, t);
            }
        }
        orow[(size_t)x * OO] = (float)(base - 2 * neg);
    }
}

// Correction: each exact-zero input element was faked as sign -1.
// For every affected (output pixel, o): out -= fx*fw with fx = -1  ->  out += fw.
__global__ void k_corrX(float* __restrict__ out) {
    int cnt = g_cntX; if (cnt > MAXZ) cnt = MAXZ;
    long long total = (long long)cnt * NTAP * OO;
    for (long long i = (long long)blockIdx.x * blockDim.x + threadIdx.x;
         i < total; i += (long long)gridDim.x * blockDim.x) {
        int zi = (int)(i / (NTAP * OO));
        int rem = (int)(i % (NTAP * OO));
        int t = rem / OO, o = rem % OO;
        int z = g_zX[zi];
        int pix = z >> 8, c = z & 255;
        int n = pix / (HH * WW);
        int y = (pix / WW) % HH;
        int x = pix % WW;
        int r = t / 3, s = t % 3;
        int yo = y - (r - 1), xo = x - (s - 1);
        if (yo < 0 || yo >= HH || xo < 0 || xo >= WW) continue;
        int fw = ((g_WS[(t * CW + (c >> 5)) * OO + o] >> (c & 31)) & 1) ? 1 : -1;
        atomicAdd(&out[(((size_t)(n * HH + yo) * WW) + xo) * OO + o], (float)fw);
    }
}

// Correction: each exact-zero weight was faked as sign -1.
// out -= fx*fw with fw = -1  ->  out += fx.
__global__ void k_corrW(float* __restrict__ out) {
    int cnt = g_cntW; if (cnt > MAXZ) cnt = MAXZ;
    long long total = (long long)cnt * PIX;
    for (long long i = (long long)blockIdx.x * blockDim.x + threadIdx.x;
         i < total; i += (long long)gridDim.x * blockDim.x) {
        int zi = (int)(i / PIX);
        int p = (int)(i % PIX);
        int z = g_zW[zi];
        int t = z >> 16, c = (z >> 8) & 255, o = z & 255;
        int r = t / 3, s = t % 3;
        int n = p / (HH * WW);
        int yo = (p / WW) % HH;
        int xo = p % WW;
        int y = yo + r - 1, x = xo + s - 1;
        if (y < 0 || y >= HH || x < 0 || x >= WW) continue;
        int pix = (n * HH + y) * WW + x;
        int fx = ((g_XS[(size_t)pix * CW + (c >> 5)] >> (c & 31)) & 1) ? 1 : -1;
        atomicAdd(&out[((size_t)p) * OO + o], (float)fx);
    }
}

// Pairs where BOTH operands were zero got corrected twice; add back fx*fw = +1.
__global__ void k_corrXW(float* __restrict__ out) {
    int cx = g_cntX; if (cx > MAXZ) cx = MAXZ;
    int cw = g_cntW; if (cw > MAXZ) cw = MAXZ;
    long long total = (long long)cx * cw;
    for (long long i = threadIdx.x; i < total; i += blockDim.x) {
        int xi = (int)(i / cw), wi = (int)(i % cw);
        int zx = g_zX[xi];
        int zw = g_zW[wi];
        int cX = zx & 255;
        int t = zw >> 16, cWc = (zw >> 8) & 255, o = zw & 255;
        if (cX != cWc) continue;
        int pix = zx >> 8;
        int n = pix / (HH * WW);
        int y = (pix / WW) % HH;
        int x = pix % WW;
        int r = t / 3, s = t % 3;
        int yo = y - (r - 1), xo = x - (s - 1);
        if (yo < 0 || yo >= HH || xo < 0 || xo >= WW) continue;
        atomicAdd(&out[(((size_t)(n * HH + yo) * WW) + xo) * OO + o], 1.0f);
    }
}

extern "C" void kernel_launch(void* const* d_in, const int* in_sizes, int n_in,
                              void* d_out, int out_size) {
    const float* x = (const float*)d_in[0];
    const float* kw = (const float*)d_in[1];
    if (n_in >= 2 && in_sizes[0] == 3 * 3 * 256 * 256 && in_sizes[1] == PIX * CC) {
        const float* tmp = x; x = kw; kw = tmp;   // defensive input-order swap
    }
    float* out = (float*)d_out;

    k_init<<<1, 1>>>();
    k_packX<<<PIX, 256>>>(x);
    k_packW<<<NTAP * CW, 256>>>(kw);
    k_main<<<NB * HH, 256>>>(out);
    k_corrX<<<64, 256>>>(out);
    k_corrW<<<256, 256>>>(out);
    k_corrXW<<<1, 256>>>(out);
}

// round 4
// speedup vs baseline: 1.6004x; 1.6004x over previous
#include <cuda_runtime.h>
#include <cstdint>

// Binary 3x3 conv, SAME pad, stride 1 — int8 tensor-core implicit GEMM.
// inputs: (32,56,56,256) f32 NHWC ; kernel: (3,3,256,256) f32 HWIO ; out: (32,56,56,256) f32
// sign() in {-1,0,+1} -> exact in s8; s32 accumulation -> bit-exact vs reference.
// Uses only sm_100-baseline ISA: mma.sync m16n8k32 s8, ldmatrix, cp.async.

#define NB 32
#define HH 56
#define WW 56
#define CC 256
#define OO 256
#define PIX (NB*HH*WW)        // 100352
#define BM 128                // pixels per CTA tile
#define NSTG 18               // 9 taps * 2 k-chunks of 128B
#define STAGE_BYTES 49152     // A 16KB + B 32KB
#define RING 4

__device__ int8_t g_X[(size_t)PIX * CC];      // sign(inputs)  [pix][c]
__device__ int8_t g_W[9 * OO * CC];           // sign(kernel)  [tap][o][c]

__device__ __forceinline__ uint32_t smem_u32(const void* p) {
    uint32_t a;
    asm("{ .reg .u64 t; cvta.to.shared.u64 t, %1; cvt.u32.u64 %0, t; }" : "=r"(a) : "l"(p));
    return a;
}
#define CP_ASYNC(dst, src, sz) \
    asm volatile("cp.async.cg.shared.global [%0], [%1], 16, %2;" :: "r"(dst), "l"(src), "r"(sz))
#define CP_COMMIT() asm volatile("cp.async.commit_group;" ::: "memory")
#define CP_WAIT(n)  asm volatile("cp.async.wait_group %0;" :: "n"(n))
#define LDSM4(r0, r1, r2, r3, a) \
    asm volatile("ldmatrix.sync.aligned.m8n8.x4.shared.b16 {%0,%1,%2,%3}, [%4];" \
                 : "=r"(r0), "=r"(r1), "=r"(r2), "=r"(r3) : "r"(a))
#define MMA(d, a, b0, b1) \
    asm volatile("mma.sync.aligned.m16n8k32.row.col.s32.s8.s8.s32 " \
                 "{%0,%1,%2,%3}, {%4,%5,%6,%7}, {%8,%9}, {%0,%1,%2,%3};" \
                 : "+r"((d)[0]), "+r"((d)[1]), "+r"((d)[2]), "+r"((d)[3]) \
                 : "r"((a)[0]), "r"((a)[1]), "r"((a)[2]), "r"((a)[3]), "r"(b0), "r"(b1))

// ---------------- prep kernels ----------------
__global__ void k_sign_x(const float* __restrict__ in) {
    size_t i = ((size_t)blockIdx.x * blockDim.x + threadIdx.x) * 16;
    int8_t o[16];
#pragma unroll
    for (int j = 0; j < 16; j += 4) {
        float4 v = *(const float4*)(in + i + j);
        o[j + 0] = v.x > 0.f ? 1 : (v.x < 0.f ? -1 : 0);
        o[j + 1] = v.y > 0.f ? 1 : (v.y < 0.f ? -1 : 0);
        o[j + 2] = v.z > 0.f ? 1 : (v.z < 0.f ? -1 : 0);
        o[j + 3] = v.w > 0.f ? 1 : (v.w < 0.f ? -1 : 0);
    }
    *(uint4*)(g_X + i) = *(uint4*)o;
}

// kernel HWIO [t][c][o] f32 -> g_W [t][o][c] s8
__global__ void k_sign_w(const float* __restrict__ kw) {
    int t = blockIdx.x >> 8;
    int c = blockIdx.x & 255;
    int o = threadIdx.x;
    float v = kw[((size_t)(t * CC + c)) * OO + o];     // coalesced in o
    g_W[((size_t)(t * OO + o)) * CC + c] = v > 0.f ? 1 : (v < 0.f ? -1 : 0);
}

// ---------------- stage loader ----------------
// Stage stg = tap*2 + kc. A: 128 rows(pixel) x 128B(k-chunk); B: 256 rows(o) x 128B.
// Smem rows are 128B with 16B-chunk XOR swizzle (chunk' = chunk ^ (row&7)).
__device__ __forceinline__ void load_stage(uint32_t sbase, int tile, int stg, int tid) {
    const int tap = stg >> 1;
    const int kc = stg & 1;
    const int dy = tap / 3 - 1, dx = tap % 3 - 1;
    const uint32_t Ab = sbase + (stg & (RING - 1)) * STAGE_BYTES;
    const uint32_t Bb = Ab + 16384;

    // A: thread -> row tid>>1, 4 chunks
    {
        const int row = tid >> 1;
        const int cb = (tid & 1) * 4;
        const int gp = tile * BM + row;
        const int n = gp / (HH * WW);
        const int rem = gp % (HH * WW);
        const int yy = rem / WW + dy;
        const int xx = rem % WW + dx;
        const bool ok = (unsigned)yy < (unsigned)HH && (unsigned)xx < (unsigned)WW;
        const uint32_t sz = ok ? 16u : 0u;
        const int8_t* src = g_X +
            (ok ? ((size_t)((n * HH + yy) * WW + xx)) * CC + kc * 128 : (size_t)0);
#pragma unroll
        for (int j = 0; j < 4; ++j) {
            const int c = cb + j;
            CP_ASYNC(Ab + row * 128 + 16 * (c ^ (row & 7)), src + c * 16, sz);
        }
    }
    // B: thread -> row o = tid, 8 chunks
    {
        const int o = tid;
        const int8_t* src = g_W + ((size_t)(tap * OO + o)) * CC + kc * 128;
#pragma unroll
        for (int c = 0; c < 8; ++c)
            CP_ASYNC(Bb + o * 128 + 16 * (c ^ (o & 7)), src + c * 16, 16u);
    }
}

// ---------------- main conv kernel ----------------
// 784 CTAs x 256 threads. 8 warps as 2(M) x 4(N); warp tile m64 x n64.
__global__ void __launch_bounds__(256, 1) k_conv(float* __restrict__ out) {
    extern __shared__ __align__(1024) char smem_raw[];
    const uint32_t sbase = smem_u32(smem_raw);
    const int tid = threadIdx.x;
    const int wid = tid >> 5;
    const int lane = tid & 31;
    const int tile = blockIdx.x;

    const int warp_m = wid >> 2;          // 0..1  -> m offset 64*warp_m
    const int warp_n = wid & 3;           // 0..3  -> n offset 64*warp_n
    const int lane7 = lane & 7;

    // ldmatrix per-lane geometry (byte rows of 16B chunks)
    const int a_row = lane7 + ((lane >> 3) & 1) * 8;   // row within m16 tile
    const int a_half = (lane >> 4) & 1;                // 16B half of 32B k-step
    const int b_row = lane7 + ((lane >> 4) & 1) * 8;
    const int b_half = (lane >> 3) & 1;

    uint32_t aoff[4], boff[4];
#pragma unroll
    for (int mf = 0; mf < 4; ++mf) aoff[mf] = (warp_m * 64 + mf * 16 + a_row) * 128;
#pragma unroll
    for (int ng = 0; ng < 4; ++ng) boff[ng] = (warp_n * 64 + ng * 16 + b_row) * 128;

    int acc[4][8][4];
#pragma unroll
    for (int mf = 0; mf < 4; ++mf)
#pragma unroll
        for (int nf = 0; nf < 8; ++nf)
#pragma unroll
            for (int q = 0; q < 4; ++q) acc[mf][nf][q] = 0;

    // prologue: fill 3 stages
    load_stage(sbase, tile, 0, tid); CP_COMMIT();
    load_stage(sbase, tile, 1, tid); CP_COMMIT();
    load_stage(sbase, tile, 2, tid); CP_COMMIT();

    for (int it = 0; it < NSTG; ++it) {
        if (it < NSTG - 2)      CP_WAIT(2);
        else if (it == NSTG - 2) CP_WAIT(1);
        else                    CP_WAIT(0);
        __syncthreads();

        const uint32_t Ab = sbase + (it & (RING - 1)) * STAGE_BYTES;
        const uint32_t Bb = Ab + 16384;

#pragma unroll
        for (int ks = 0; ks < 4; ++ks) {
            uint32_t a[4][4], b[4][4];
#pragma unroll
            for (int mf = 0; mf < 4; ++mf)
                LDSM4(a[mf][0], a[mf][1], a[mf][2], a[mf][3],
                      Ab + aoff[mf] + 16 * ((2 * ks + a_half) ^ lane7));
#pragma unroll
            for (int ng = 0; ng < 4; ++ng)
                LDSM4(b[ng][0], b[ng][1], b[ng][2], b[ng][3],
                      Bb + boff[ng] + 16 * ((2 * ks + b_half) ^ lane7));
#pragma unroll
            for (int mf = 0; mf < 4; ++mf)
#pragma unroll
                for (int ng = 0; ng < 4; ++ng) {
                    MMA(acc[mf][2 * ng],     a[mf], b[ng][0], b[ng][1]);
                    MMA(acc[mf][2 * ng + 1], a[mf], b[ng][2], b[ng][3]);
                }
        }

        if (it + 3 < NSTG) {
            __syncthreads();                    // all warps done with buffer (it-1)
            load_stage(sbase, tile, it + 3, tid);
            CP_COMMIT();
        }
    }

    // ---- epilogue: s32 -> f32 (exact), store ----
    const int row_base = tile * BM + warp_m * 64 + (lane >> 2);
    const int col_base = warp_n * 64 + 2 * (lane & 3);
#pragma unroll
    for (int mf = 0; mf < 4; ++mf) {
        const int r0 = row_base + mf * 16;
#pragma unroll
        for (int nf = 0; nf < 8; ++nf) {
            const int c = col_base + nf * 8;
            float2 lo = make_float2((float)acc[mf][nf][0], (float)acc[mf][nf][1]);
            float2 hi = make_float2((float)acc[mf][nf][2], (float)acc[mf][nf][3]);
            *(float2*)(out + (size_t)r0 * OO + c) = lo;
            *(float2*)(out + (size_t)(r0 + 8) * OO + c) = hi;
        }
    }
}

// ---------------- launch ----------------
extern "C" void kernel_launch(void* const* d_in, const int* in_sizes, int n_in,
                              void* d_out, int out_size) {
    const float* x = (const float*)d_in[0];
    const float* kw = (const float*)d_in[1];
    if (n_in >= 2 && in_sizes[0] == 9 * CC * OO && in_sizes[1] == (int)((size_t)PIX * CC)) {
        const float* t = x; x = kw; kw = t;     // defensive input-order swap
    }
    float* out = (float*)d_out;

    static bool attr_set = false;
    if (!attr_set) {
        cudaFuncSetAttribute(k_conv, cudaFuncAttributeMaxDynamicSharedMemorySize,
                             RING * STAGE_BYTES);
        attr_set = true;
    }

    k_sign_x<<<(PIX * CC) / (256 * 16), 256>>>(x);
    k_sign_w<<<9 * 256, 256>>>(kw);
    k_conv<<<PIX / BM, 256, RING * STAGE_BYTES>>>(out);
}

// round 6
// speedup vs baseline: 1.6210x; 1.0129x over previous
#include <cuda_runtime.h>
#include <cstdint>

// Binary 3x3 conv, SAME pad, stride 1 — int8 tensor-core implicit GEMM.
// inputs: (32,56,56,256) f32 NHWC ; kernel: (3,3,256,256) f32 HWIO ; out: (32,56,56,256) f32
// sign() in {-1,0,+1} -> exact in s8; s32 accumulation -> bit-exact vs reference.
// sm_100-baseline ISA only: mma.sync m16n8k32 s8, ldmatrix, cp.async.

#define NB 32
#define HH 56
#define WW 56
#define CC 256
#define OO 256
#define PIX (NB*HH*WW)        // 100352
#define BM 128                // pixels per CTA tile
#define NSTG 18               // 9 taps * 2 k-chunks of 128B
#define STAGE_BYTES 49152     // A 16KB + B 32KB
#define RING 4

__device__ int8_t g_X[(size_t)PIX * CC];      // sign(inputs)  [pix][c]
__device__ int8_t g_W[9 * OO * CC];           // sign(kernel)  [tap][o][c]

__device__ __forceinline__ uint32_t smem_u32(const void* p) {
    uint32_t a;
    asm("{ .reg .u64 t; cvta.to.shared.u64 t, %1; cvt.u32.u64 %0, t; }" : "=r"(a) : "l"(p));
    return a;
}
#define CP_ASYNC(dst, src, sz) \
    asm volatile("cp.async.cg.shared.global [%0], [%1], 16, %2;" :: "r"(dst), "l"(src), "r"(sz))
#define CP_COMMIT() asm volatile("cp.async.commit_group;" ::: "memory")
#define CP_WAIT(n)  asm volatile("cp.async.wait_group %0;" :: "n"(n))
#define LDSM4(r0, r1, r2, r3, a) \
    asm volatile("ldmatrix.sync.aligned.m8n8.x4.shared.b16 {%0,%1,%2,%3}, [%4];" \
                 : "=r"(r0), "=r"(r1), "=r"(r2), "=r"(r3) : "r"(a))
#define MMA(d, a, b0, b1) \
    asm volatile("mma.sync.aligned.m16n8k32.row.col.s32.s8.s8.s32 " \
                 "{%0,%1,%2,%3}, {%4,%5,%6,%7}, {%8,%9}, {%0,%1,%2,%3};" \
                 : "+r"((d)[0]), "+r"((d)[1]), "+r"((d)[2]), "+r"((d)[3]) \
                 : "r"((a)[0]), "r"((a)[1]), "r"((a)[2]), "r"((a)[3]), "r"(b0), "r"(b1))

// ---------------- prep kernels ----------------
__global__ void k_sign_x(const float* __restrict__ in) {
    size_t i = ((size_t)blockIdx.x * blockDim.x + threadIdx.x) * 16;
    int8_t o[16];
#pragma unroll
    for (int j = 0; j < 16; j += 4) {
        float4 v = *(const float4*)(in + i + j);
        o[j + 0] = v.x > 0.f ? 1 : (v.x < 0.f ? -1 : 0);
        o[j + 1] = v.y > 0.f ? 1 : (v.y < 0.f ? -1 : 0);
        o[j + 2] = v.z > 0.f ? 1 : (v.z < 0.f ? -1 : 0);
        o[j + 3] = v.w > 0.f ? 1 : (v.w < 0.f ? -1 : 0);
    }
    *(uint4*)(g_X + i) = *(uint4*)o;
}

// kernel HWIO [t][c][o] f32 -> g_W [t][o][c] s8
__global__ void k_sign_w(const float* __restrict__ kw) {
    int t = blockIdx.x >> 8;
    int c = blockIdx.x & 255;
    int o = threadIdx.x;
    float v = kw[((size_t)(t * CC + c)) * OO + o];     // coalesced in o
    g_W[((size_t)(t * OO + o)) * CC + c] = v > 0.f ? 1 : (v < 0.f ? -1 : 0);
}

// ---------------- stage loader ----------------
// Stage stg = tap*2 + kc. A: 128 rows(pixel) x 128B; B: 256 rows(o) x 128B.
// Smem rows are 128B with 16B-chunk XOR swizzle (chunk' = chunk ^ (row&7)).
struct AGeom { int n, y, x; int row, cb; };

__device__ __forceinline__ void load_stage(uint32_t sbase, const AGeom& ag,
                                           int stg, int tid) {
    const int tap = stg >> 1;
    const int kc = stg & 1;
    const uint32_t Ab = sbase + (stg & (RING - 1)) * STAGE_BYTES;
    const uint32_t Bb = Ab + 16384;

    // A
    {
        const int yy = ag.y + tap / 3 - 1;
        const int xx = ag.x + tap % 3 - 1;
        const bool ok = (unsigned)yy < (unsigned)HH && (unsigned)xx < (unsigned)WW;
        const uint32_t sz = ok ? 16u : 0u;
        const int8_t* src = g_X +
            (ok ? ((size_t)((ag.n * HH + yy) * WW + xx)) * CC + kc * 128 : (size_t)0);
#pragma unroll
        for (int j = 0; j < 4; ++j) {
            const int c = ag.cb + j;
            CP_ASYNC(Ab + ag.row * 128 + 16 * (c ^ (ag.row & 7)), src + c * 16, sz);
        }
    }
    // B
    {
        const int8_t* src = g_W + ((size_t)(tap * OO + tid)) * CC + kc * 128;
#pragma unroll
        for (int c = 0; c < 8; ++c)
            CP_ASYNC(Bb + tid * 128 + 16 * (c ^ (tid & 7)), src + c * 16, 16u);
    }
}

// ---------------- main conv kernel ----------------
// 784 CTAs x 256 threads. 8 warps as 2(M) x 4(N); warp tile m64 x n64.
__global__ void __launch_bounds__(256, 1) k_conv(float* __restrict__ out) {
    extern __shared__ __align__(1024) char smem_raw[];
    const uint32_t sbase = smem_u32(smem_raw);
    const int tid = threadIdx.x;
    const int wid = tid >> 5;
    const int lane = tid & 31;
    const int tile = blockIdx.x;

    const int warp_m = wid >> 2;
    const int warp_n = wid & 3;
    const int lane7 = lane & 7;

    AGeom ag;
    ag.row = tid >> 1;
    ag.cb = (tid & 1) * 4;
    {
        const int gp = tile * BM + ag.row;
        ag.n = gp / (HH * WW);
        const int rem = gp % (HH * WW);
        ag.y = rem / WW;
        ag.x = rem % WW;
    }

    const int a_row = lane7 + ((lane >> 3) & 1) * 8;
    const int a_half = (lane >> 4) & 1;
    const int b_row = lane7 + ((lane >> 4) & 1) * 8;
    const int b_half = (lane >> 3) & 1;

    uint32_t aoff[4], boff[4];
#pragma unroll
    for (int mf = 0; mf < 4; ++mf) aoff[mf] = (warp_m * 64 + mf * 16 + a_row) * 128;
#pragma unroll
    for (int ng = 0; ng < 4; ++ng) boff[ng] = (warp_n * 64 + ng * 16 + b_row) * 128;

    int acc[4][8][4];
#pragma unroll
    for (int mf = 0; mf < 4; ++mf)
#pragma unroll
        for (int nf = 0; nf < 8; ++nf)
#pragma unroll
            for (int q = 0; q < 4; ++q) acc[mf][nf][q] = 0;

    // prologue: fill 3 stages
    load_stage(sbase, ag, 0, tid); CP_COMMIT();
    load_stage(sbase, ag, 1, tid); CP_COMMIT();
    load_stage(sbase, ag, 2, tid); CP_COMMIT();

    for (int it = 0; it < NSTG; ++it) {
        if (it < NSTG - 2)       CP_WAIT(2);
        else if (it == NSTG - 2) CP_WAIT(1);
        else                     CP_WAIT(0);
        __syncthreads();
        // Buffer (it-1)&3 is free here: every warp's ldmatrix reads of it-1
        // completed before its MMA issues, which precede this barrier.
        if (it + 3 < NSTG) {
            load_stage(sbase, ag, it + 3, tid);   // overlaps the MMA body below
            CP_COMMIT();
        }

        const uint32_t Ab = sbase + (it & (RING - 1)) * STAGE_BYTES;
        const uint32_t Bb = Ab + 16384;

#pragma unroll
        for (int ks = 0; ks < 4; ++ks) {
            uint32_t a[4][4], b[4][4];
#pragma unroll
            for (int mf = 0; mf < 4; ++mf)
                LDSM4(a[mf][0], a[mf][1], a[mf][2], a[mf][3],
                      Ab + aoff[mf] + 16 * ((2 * ks + a_half) ^ lane7));
#pragma unroll
            for (int ng = 0; ng < 4; ++ng)
                LDSM4(b[ng][0], b[ng][1], b[ng][2], b[ng][3],
                      Bb + boff[ng] + 16 * ((2 * ks + b_half) ^ lane7));
#pragma unroll
            for (int mf = 0; mf < 4; ++mf)
#pragma unroll
                for (int ng = 0; ng < 4; ++ng) {
                    MMA(acc[mf][2 * ng],     a[mf], b[ng][0], b[ng][1]);
                    MMA(acc[mf][2 * ng + 1], a[mf], b[ng][2], b[ng][3]);
                }
        }
    }

    // ---- epilogue: s32 -> f32 (exact), store ----
    const int row_base = tile * BM + warp_m * 64 + (lane >> 2);
    const int col_base = warp_n * 64 + 2 * (lane & 3);
#pragma unroll
    for (int mf = 0; mf < 4; ++mf) {
        const int r0 = row_base + mf * 16;
#pragma unroll
        for (int nf = 0; nf < 8; ++nf) {
            const int c = col_base + nf * 8;
            float2 lo = make_float2((float)acc[mf][nf][0], (float)acc[mf][nf][1]);
            float2 hi = make_float2((float)acc[mf][nf][2], (float)acc[mf][nf][3]);
            *(float2*)(out + (size_t)r0 * OO + c) = lo;
            *(float2*)(out + (size_t)(r0 + 8) * OO + c) = hi;
        }
    }
}

// ---------------- launch ----------------
extern "C" void kernel_launch(void* const* d_in, const int* in_sizes, int n_in,
                              void* d_out, int out_size) {
    const float* x = (const float*)d_in[0];
    const float* kw = (const float*)d_in[1];
    if (n_in >= 2 && in_sizes[0] == 9 * CC * OO && in_sizes[1] == (int)((size_t)PIX * CC)) {
        const float* t = x; x = kw; kw = t;     // defensive input-order swap
    }
    float* out = (float*)d_out;

    // Unconditional (idempotent, capture-safe) — no static guards allowed.
    cudaFuncSetAttribute(k_conv, cudaFuncAttributeMaxDynamicSharedMemorySize,
                         RING * STAGE_BYTES);

    k_sign_x<<<(PIX * CC) / (256 * 16), 256>>>(x);
    k_sign_w<<<9 * 256, 256>>>(kw);
    k_conv<<<PIX / BM, 256, RING * STAGE_BYTES>>>(out);
}